// round 13
// baseline (speedup 1.0000x reference)
#include <cuda_runtime.h>
#include <cuda_fp16.h>
#include <cstdint>
#include <math.h>

#define BATCH 256
#define NI    1152
#define NO    10
#define DOUT  16
#define DIN   8
#define OD    160          // NO * DOUT

// ---------------- scratch ----------------
__device__ __half g_xhat[(size_t)BATCH * NI * OD];   // [b][i][od] fp16, 94.5MB (L2-resident)

// ---------------- packed fp32x2 helpers (sm_103a) ----------------
typedef unsigned long long ull;
__device__ __forceinline__ ull pack2(float x, float y) {
    ull r; asm("mov.b64 %0, {%1, %2};" : "=l"(r) : "f"(x), "f"(y)); return r;
}
__device__ __forceinline__ float2 unpk2(ull v) {
    float2 r; asm("mov.b64 {%0, %1}, %2;" : "=f"(r.x), "=f"(r.y) : "l"(v)); return r;
}
__device__ __forceinline__ ull ffma2(ull a, ull b, ull c) {
    ull d; asm("fma.rn.f32x2 %0, %1, %2, %3;" : "=l"(d) : "l"(a), "l"(b), "l"(c)); return d;
}

// ---------------- cluster helpers ----------------
__device__ __forceinline__ void cluster_sync_() {
    asm volatile("barrier.cluster.arrive.aligned;" ::: "memory");
    asm volatile("barrier.cluster.wait.aligned;" ::: "memory");
}
__device__ __forceinline__ unsigned int smem_u32(const void* p) {
    unsigned int a;
    asm("{ .reg .u64 t; cvta.to.shared.u64 t, %1; cvt.u32.u64 %0, t; }" : "=r"(a) : "l"(p));
    return a;
}
__device__ __forceinline__ void st_remote_f32(unsigned int saddr, unsigned int peer, float v) {
    unsigned int ra;
    asm volatile("mapa.shared::cluster.u32 %0, %1, %2;" : "=r"(ra) : "r"(saddr), "r"(peer));
    asm volatile("st.shared::cluster.f32 [%0], %1;" :: "r"(ra), "f"(v) : "memory");
}

// =====================================================================
// Kernel 1 (stable, ~21us): thread owns (i, od-octet), 64 weight floats
// register-resident across 64 batches, one STG.128 per batch.
// =====================================================================
#define K1_IT 16
#define K1_BT 64

__global__ __launch_bounds__(320) void k1_xhat(const float* __restrict__ x,
                                               const float* __restrict__ w)
{
    __shared__ ull xs2[K1_BT][K1_IT * DIN];   // (x,x) packed, 64KB

    const int i0 = blockIdx.x * K1_IT;
    const int b0 = blockIdx.y * K1_BT;
    const int tid = threadIdx.x;

    for (int u = tid; u < K1_BT * K1_IT * DIN; u += 320) {
        int bl = u >> 7, c128 = u & 127;
        float v = x[(size_t)(b0 + bl) * (NI * DIN) + (size_t)i0 * DIN + c128];
        xs2[bl][c128] = pack2(v, v);
    }

    const int il  = tid / 20;
    const int oct = tid % 20;
    const int i   = i0 + il;
    const int o   = oct >> 1;
    const int d0  = (oct & 1) * 8;

    const float4* wp = (const float4*)&w[(((size_t)o * NI + i) * 16 + d0) * 8];
    float wf[64];
    #pragma unroll
    for (int k = 0; k < 16; k++) ((float4*)wf)[k] = wp[k];
    ull pw[4][8];
    #pragma unroll
    for (int p = 0; p < 4; p++)
        #pragma unroll
        for (int c = 0; c < 8; c++)
            pw[p][c] = pack2(wf[(2 * p) * 8 + c], wf[(2 * p + 1) * 8 + c]);
    __syncthreads();

    const ull* xrow0 = &xs2[0][il * 8];
    #pragma unroll 2
    for (int b = 0; b < K1_BT; b++) {
        const ull* xr = xrow0 + (size_t)b * (K1_IT * DIN);
        ull a0 = 0ull, a1 = 0ull, a2 = 0ull, a3 = 0ull;
        #pragma unroll
        for (int c = 0; c < 8; c++) {
            ull xx = xr[c];
            a0 = ffma2(pw[0][c], xx, a0);
            a1 = ffma2(pw[1][c], xx, a1);
            a2 = ffma2(pw[2][c], xx, a2);
            a3 = ffma2(pw[3][c], xx, a3);
        }
        float2 f0 = unpk2(a0), f1 = unpk2(a1), f2 = unpk2(a2), f3 = unpk2(a3);
        union { __half2 h; unsigned int u; } c0, c1, c2, c3;
        c0.h = __float22half2_rn(f0);
        c1.h = __float22half2_rn(f1);
        c2.h = __float22half2_rn(f2);
        c3.h = __float22half2_rn(f3);
        size_t base = ((size_t)(b0 + b) * NI + i) * OD + 8 * oct;
        *(uint4*)(g_xhat + base) = make_uint4(c0.u, c1.u, c2.u, c3.u);
    }
}

// =====================================================================
// Kernel 2: fused routing, 4-CTA cluster per batch (288 rows/CTA),
// 320 threads/CTA, ~17KB smem -> 3 CTAs/SM. NO smem staging: s0/p1/p2
// stream x_hat straight from L2. Shfl-free phases; half2 acc (flush/4);
// double-buffered DSMEM exchange; register-resident t-pair epilogue.
// =====================================================================
#define K2_THREADS 320
#define CLS   4
#define NIH   288             // i-rows per CTA
#define NCH   8               // reduce chunks (36 rows each, 40 quads -> 320 thr)

// dynamic smem layout (bytes) — all 16B-aligned
#define C_OFF     0                            // [288][10] fp16
#define C_SZ      (NIH * NO * 2)               // 5,760
#define PACC_OFF  (C_OFF + C_SZ)               // [8][160] f32
#define PACC_SZ   (NCH * OD * 4)               // 5,120
#define SLOT0_OFF (PACC_OFF + PACC_SZ)         // [4][160] f32
#define SLOT_SZ   (CLS * OD * 4)               // 2,560
#define SLOT1_OFF (SLOT0_OFF + SLOT_SZ)
#define TH2_OFF   (SLOT1_OFF + SLOT_SZ)        // [80] half2
#define TH2_SZ    320
#define K2_SMEM   (TH2_OFF + TH2_SZ)           // 16,320 B

__global__ __cluster_dims__(CLS, 1, 1) __launch_bounds__(K2_THREADS, 3)
void k2_route(float* __restrict__ dout)
{
    extern __shared__ __align__(16) char sm[];
    __half*  cbuf = (__half*)(sm + C_OFF);
    float*   pacc = (float*)(sm + PACC_OFF);
    __half2* th2  = (__half2*)(sm + TH2_OFF);

    const int cta = blockIdx.x;
    const int b   = cta >> 2;
    const unsigned int rank = cta & 3;
    const int tid = threadIdx.x;
    const int q   = tid % 40;     // od-quad
    const int ch  = tid / 40;     // chunk 0..7
    const int o_q = q >> 2;

    const unsigned int sqmask = (tid < 64) ? 0xffffffffu : 0x0000ffffu;
    float2 t2 = make_float2(0.f, 0.f);   // register-resident t pair (tid<80)

    const __half* gsrc = g_xhat + ((size_t)b * NI + (size_t)rank * NIH) * OD;

    // ---- s0 partial: thread = (ch, quad), 36 rows from L2, half2 acc/4
    {
        float4 fa = make_float4(0.f, 0.f, 0.f, 0.f);
        #pragma unroll
        for (int g4 = 0; g4 < 9; g4++) {
            __half2 a01 = __float2half2_rn(0.f), a23 = __float2half2_rn(0.f);
            #pragma unroll
            for (int kk = 0; kk < 4; kk++) {
                const int row = ch * 36 + g4 * 4 + kk;
                uint2 v = *(const uint2*)(gsrc + (size_t)row * OD + q * 4);
                a01 = __hadd2(a01, *(__half2*)&v.x);
                a23 = __hadd2(a23, *(__half2*)&v.y);
            }
            float2 f01 = __half22float2(a01), f23 = __half22float2(a23);
            fa.x += f01.x; fa.y += f01.y; fa.z += f23.x; fa.w += f23.y;
        }
        *(float4*)&pacc[ch * OD + q * 4] = fa;
    }
    __syncthreads();

    // ---- exchange 0 (buf0): s0; squash pairs -> t2 regs + th2 ----
    {
        float* slot = (float*)(sm + SLOT0_OFF);
        if (tid < OD) {
            float pv = 0.f;
            #pragma unroll
            for (int c2 = 0; c2 < NCH; c2++) pv += pacc[c2 * OD + tid];
            slot[rank * OD + tid] = pv;
            unsigned int sa = smem_u32(&slot[rank * OD + tid]);
            #pragma unroll
            for (int r = 1; r < CLS; r++) st_remote_f32(sa, rank ^ r, pv);
        }
        cluster_sync_();
        if (tid < 80) {
            float sa = (slot[0 * OD + 2 * tid] + slot[1 * OD + 2 * tid] +
                        slot[2 * OD + 2 * tid] + slot[3 * OD + 2 * tid]) * 0.1f;
            float sb = (slot[0 * OD + 2 * tid + 1] + slot[1 * OD + 2 * tid + 1] +
                        slot[2 * OD + 2 * tid + 1] + slot[3 * OD + 2 * tid + 1]) * 0.1f;
            float v = sa * sa + sb * sb;
            v += __shfl_xor_sync(sqmask, v, 4);
            v += __shfl_xor_sync(sqmask, v, 2);
            v += __shfl_xor_sync(sqmask, v, 1);
            float sc = (v / (1.0f + v)) / (sqrtf(v) + 1e-8f);
            t2.x = sa * sc; t2.y = sb * sc;
            th2[tid] = __floats2half2_rn(t2.x, t2.y);
        }
    }
    __syncthreads();

    // ---- two routing passes ----
    #pragma unroll 1
    for (int pass = 0; pass < 2; pass++) {
        // ===== phase 1: thread = one i (288 threads); L2 row + half2 dots
        if (tid < NIH) {
            const __half* row = gsrc + (size_t)tid * OD;
            float e[NO];
            #pragma unroll
            for (int o = 0; o < NO; o++) {
                uint4 xa = *(const uint4*)(row + o * 16);
                uint4 xb = *(const uint4*)(row + o * 16 + 8);
                uint4 ta = *(const uint4*)((const char*)th2 + o * 32);
                uint4 tb = *(const uint4*)((const char*)th2 + o * 32 + 16);
                __half2 acc = __hmul2(*(__half2*)&xa.x, *(__half2*)&ta.x);
                acc = __hfma2(*(__half2*)&xa.y, *(__half2*)&ta.y, acc);
                acc = __hfma2(*(__half2*)&xa.z, *(__half2*)&ta.z, acc);
                acc = __hfma2(*(__half2*)&xa.w, *(__half2*)&ta.w, acc);
                acc = __hfma2(*(__half2*)&xb.x, *(__half2*)&tb.x, acc);
                acc = __hfma2(*(__half2*)&xb.y, *(__half2*)&tb.y, acc);
                acc = __hfma2(*(__half2*)&xb.z, *(__half2*)&tb.z, acc);
                acc = __hfma2(*(__half2*)&xb.w, *(__half2*)&tb.w, acc);
                float2 f = __half22float2(acc);
                e[o] = f.x + f.y;
            }
            float m = e[0];
            #pragma unroll
            for (int o = 1; o < NO; o++) m = fmaxf(m, e[o]);
            float sum = 0.f;
            #pragma unroll
            for (int o = 0; o < NO; o++) { e[o] = __expf(e[o] - m); sum += e[o]; }
            const float inv = 1.0f / sum;
            __half2* cp = (__half2*)(cbuf + tid * NO);
            #pragma unroll
            for (int p = 0; p < 5; p++)
                cp[p] = __floats2half2_rn(e[2 * p] * inv, e[2 * p + 1] * inv);
        }
        __syncthreads();

        // ===== phase 2: thread = (ch, quad); L2 rows, half2 acc of c*xh
        {
            float4 fa = make_float4(0.f, 0.f, 0.f, 0.f);
            #pragma unroll
            for (int g4 = 0; g4 < 9; g4++) {
                __half2 a01 = __float2half2_rn(0.f), a23 = __float2half2_rn(0.f);
                #pragma unroll
                for (int kk = 0; kk < 4; kk++) {
                    const int row = ch * 36 + g4 * 4 + kk;
                    uint2 v = *(const uint2*)(gsrc + (size_t)row * OD + q * 4);
                    __half2 c2 = __half2half2(cbuf[row * NO + o_q]);
                    a01 = __hfma2(*(__half2*)&v.x, c2, a01);
                    a23 = __hfma2(*(__half2*)&v.y, c2, a23);
                }
                float2 f01 = __half22float2(a01), f23 = __half22float2(a23);
                fa.x += f01.x; fa.y += f01.y; fa.z += f23.x; fa.w += f23.y;
            }
            *(float4*)&pacc[ch * OD + q * 4] = fa;
        }
        __syncthreads();

        // ===== exchange (alternating buffer) + squash pairs
        {
            float* slot = (float*)(sm + ((pass == 0) ? SLOT1_OFF : SLOT0_OFF));
            if (tid < OD) {
                float pv = 0.f;
                #pragma unroll
                for (int c2 = 0; c2 < NCH; c2++) pv += pacc[c2 * OD + tid];
                slot[rank * OD + tid] = pv;
                unsigned int sa = smem_u32(&slot[rank * OD + tid]);
                #pragma unroll
                for (int r = 1; r < CLS; r++) st_remote_f32(sa, rank ^ r, pv);
            }
            cluster_sync_();
            if (tid < 80) {
                float sa = slot[0 * OD + 2 * tid] + slot[1 * OD + 2 * tid] +
                           slot[2 * OD + 2 * tid] + slot[3 * OD + 2 * tid];
                float sb = slot[0 * OD + 2 * tid + 1] + slot[1 * OD + 2 * tid + 1] +
                           slot[2 * OD + 2 * tid + 1] + slot[3 * OD + 2 * tid + 1];
                float v = sa * sa + sb * sb;
                v += __shfl_xor_sync(sqmask, v, 4);
                v += __shfl_xor_sync(sqmask, v, 2);
                v += __shfl_xor_sync(sqmask, v, 1);
                float sc = (v / (1.0f + v)) / (sqrtf(v) + 1e-8f);
                if (pass == 0) {
                    t2.x += sa * sc; t2.y += sb * sc;        // t = out0 + out1
                    th2[tid] = __floats2half2_rn(t2.x, t2.y);
                } else if (rank == 0) {
                    *(float2*)&dout[b * OD + 2 * tid] = make_float2(sa * sc, sb * sc);
                }
            }
        }
        __syncthreads();
    }
}

// =====================================================================
extern "C" void kernel_launch(void* const* d_in, const int* in_sizes, int n_in,
                              void* d_out, int out_size)
{
    const float* x = (const float*)d_in[0];   // [256,1152,8]
    const float* w = (const float*)d_in[1];   // [10,1152,16,8]
    float* out = (float*)d_out;               // [256,10,16]

    cudaFuncSetAttribute(k2_route, cudaFuncAttributeMaxDynamicSharedMemorySize, K2_SMEM);

    k1_xhat<<<dim3(NI / K1_IT, BATCH / K1_BT), 320>>>(x, w);
    k2_route<<<CLS * BATCH, K2_THREADS, K2_SMEM>>>(out);
}

// round 14
// speedup vs baseline: 1.4286x; 1.4286x over previous
#include <cuda_runtime.h>
#include <cuda_fp16.h>
#include <cstdint>
#include <math.h>

#define BATCH 256
#define NI    1152
#define NO    10
#define DOUT  16
#define DIN   8
#define OD    160          // NO * DOUT

// ---------------- scratch ----------------
__device__ __half g_xhat[(size_t)BATCH * NI * OD];   // [b][i][od] fp16, 94.5MB

// ---------------- packed fp32x2 helpers (sm_103a) ----------------
typedef unsigned long long ull;
__device__ __forceinline__ ull pack2(float x, float y) {
    ull r; asm("mov.b64 %0, {%1, %2};" : "=l"(r) : "f"(x), "f"(y)); return r;
}
__device__ __forceinline__ float2 unpk2(ull v) {
    float2 r; asm("mov.b64 {%0, %1}, %2;" : "=f"(r.x), "=f"(r.y) : "l"(v)); return r;
}
__device__ __forceinline__ ull ffma2(ull a, ull b, ull c) {
    ull d; asm("fma.rn.f32x2 %0, %1, %2, %3;" : "=l"(d) : "l"(a), "l"(b), "l"(c)); return d;
}

// ---------------- cluster / async helpers ----------------
__device__ __forceinline__ void cluster_sync_() {
    asm volatile("barrier.cluster.arrive.aligned;" ::: "memory");
    asm volatile("barrier.cluster.wait.aligned;" ::: "memory");
}
__device__ __forceinline__ unsigned int smem_u32(const void* p) {
    unsigned int a;
    asm("{ .reg .u64 t; cvta.to.shared.u64 t, %1; cvt.u32.u64 %0, t; }" : "=r"(a) : "l"(p));
    return a;
}
__device__ __forceinline__ void st_remote_f32(unsigned int saddr, unsigned int peer, float v) {
    unsigned int ra;
    asm volatile("mapa.shared::cluster.u32 %0, %1, %2;" : "=r"(ra) : "r"(saddr), "r"(peer));
    asm volatile("st.shared::cluster.f32 [%0], %1;" :: "r"(ra), "f"(v) : "memory");
}
__device__ __forceinline__ void cp_async16(unsigned int sdst, const void* gsrc) {
    asm volatile("cp.async.cg.shared.global [%0], [%1], 16;" :: "r"(sdst), "l"(gsrc) : "memory");
}

// =====================================================================
// Kernel 1 (stable, ~21us): thread owns (i, od-octet), 64 weight floats
// register-resident across 64 batches, one STG.128 per batch.
// =====================================================================
#define K1_IT 16
#define K1_BT 64

__global__ __launch_bounds__(320) void k1_xhat(const float* __restrict__ x,
                                               const float* __restrict__ w)
{
    __shared__ ull xs2[K1_BT][K1_IT * DIN];   // (x,x) packed, 64KB

    const int i0 = blockIdx.x * K1_IT;
    const int b0 = blockIdx.y * K1_BT;
    const int tid = threadIdx.x;

    for (int u = tid; u < K1_BT * K1_IT * DIN; u += 320) {
        int bl = u >> 7, c128 = u & 127;
        float v = x[(size_t)(b0 + bl) * (NI * DIN) + (size_t)i0 * DIN + c128];
        xs2[bl][c128] = pack2(v, v);
    }

    const int il  = tid / 20;
    const int oct = tid % 20;
    const int i   = i0 + il;
    const int o   = oct >> 1;
    const int d0  = (oct & 1) * 8;

    const float4* wp = (const float4*)&w[(((size_t)o * NI + i) * 16 + d0) * 8];
    float wf[64];
    #pragma unroll
    for (int k = 0; k < 16; k++) ((float4*)wf)[k] = wp[k];
    ull pw[4][8];
    #pragma unroll
    for (int p = 0; p < 4; p++)
        #pragma unroll
        for (int c = 0; c < 8; c++)
            pw[p][c] = pack2(wf[(2 * p) * 8 + c], wf[(2 * p + 1) * 8 + c]);
    __syncthreads();

    const ull* xrow0 = &xs2[0][il * 8];
    #pragma unroll 2
    for (int b = 0; b < K1_BT; b++) {
        const ull* xr = xrow0 + (size_t)b * (K1_IT * DIN);
        ull a0 = 0ull, a1 = 0ull, a2 = 0ull, a3 = 0ull;
        #pragma unroll
        for (int c = 0; c < 8; c++) {
            ull xx = xr[c];
            a0 = ffma2(pw[0][c], xx, a0);
            a1 = ffma2(pw[1][c], xx, a1);
            a2 = ffma2(pw[2][c], xx, a2);
            a3 = ffma2(pw[3][c], xx, a3);
        }
        float2 f0 = unpk2(a0), f1 = unpk2(a1), f2 = unpk2(a2), f3 = unpk2(a3);
        union { __half2 h; unsigned int u; } c0, c1, c2, c3;
        c0.h = __float22half2_rn(f0);
        c1.h = __float22half2_rn(f1);
        c2.h = __float22half2_rn(f2);
        c3.h = __float22half2_rn(f3);
        size_t base = ((size_t)(b0 + b) * NI + i) * OD + 8 * oct;
        *(uint4*)(g_xhat + base) = make_uint4(c0.u, c1.u, c2.u, c3.u);
    }
}

// =====================================================================
// Kernel 2: fused routing, 4-CTA cluster per batch (288 rows/CTA),
// 384 threads/CTA, 2 CTAs/SM. 3-group cp.async fill with s0 processed
// group-by-group under the in-flight copy. Shfl-free p1/p2; half2 acc
// (flush/4); double-buffered DSMEM exchange; register t-pair epilogue.
// =====================================================================
#define K2_THREADS 384
#define CLS   4
#define NIH   288             // i-rows per CTA
#define ROWB  336             // padded row stride (21 x 16B)
#define NCH_S0 8              // s0 chunks: 320 thr, 12 rows per group (36 total)
#define NCH_P2 9              // p2 chunks: 360 thr, 32 rows each

// dynamic smem layout (bytes) — all 16B-aligned
#define XH_OFF    0
#define XH_SZ     (NIH * ROWB)                 // 96,768
#define C_OFF     (XH_OFF + XH_SZ)             // [288][10] fp16
#define C_SZ      (NIH * NO * 2)               // 5,760
#define PACC_OFF  (C_OFF + C_SZ)               // [9][160] f32
#define PACC_SZ   (NCH_P2 * OD * 4)            // 5,760
#define SLOT0_OFF (PACC_OFF + PACC_SZ)         // [4][160] f32
#define SLOT_SZ   (CLS * OD * 4)               // 2,560
#define SLOT1_OFF (SLOT0_OFF + SLOT_SZ)
#define TH2_OFF   (SLOT1_OFF + SLOT_SZ)        // [80] half2
#define TH2_SZ    320
#define K2_SMEM   (TH2_OFF + TH2_SZ)           // 113,728 B (x2 per SM)

__global__ __cluster_dims__(CLS, 1, 1) __launch_bounds__(K2_THREADS, 2)
void k2_route(float* __restrict__ dout)
{
    extern __shared__ __align__(16) char sm[];
    char*    xhb  = sm + XH_OFF;
    __half*  cbuf = (__half*)(sm + C_OFF);
    float*   pacc = (float*)(sm + PACC_OFF);
    __half2* th2  = (__half2*)(sm + TH2_OFF);

    const int cta = blockIdx.x;
    const int b   = cta >> 2;
    const unsigned int rank = cta & 3;
    const int tid = threadIdx.x;
    const int q   = tid % 40;     // od-quad
    const int chS = tid / 40;     // s0 chunk (0..7 valid)
    const int o_q = q >> 2;

    const unsigned int sqmask = (tid < 64) ? 0xffffffffu : 0x0000ffffu;
    float2 t2 = make_float2(0.f, 0.f);   // register-resident t pair (tid<80)

    const __half* gsrc = g_xhat + ((size_t)b * NI + (size_t)rank * NIH) * OD;
    const unsigned int xh_s = smem_u32(xhb);

    // ---- issue async copy in 3 groups of 96 rows each ----
    #pragma unroll
    for (int g = 0; g < 3; g++) {
        #pragma unroll
        for (int t = 0; t < 5; t++) {
            int e = tid + (g * 5 + t) * K2_THREADS;     // rows [96g, 96g+96)
            int row = e / 20, u = e % 20;
            cp_async16(xh_s + row * ROWB + u * 16, gsrc + (size_t)e * 8);
        }
        asm volatile("cp.async.commit_group;" ::: "memory");
    }

    // ---- s0: process each 96-row group as soon as it lands ----
    float4 fa = make_float4(0.f, 0.f, 0.f, 0.f);
    #pragma unroll
    for (int g = 0; g < 3; g++) {
        if (g == 0)      asm volatile("cp.async.wait_group 2;" ::: "memory");
        else if (g == 1) asm volatile("cp.async.wait_group 1;" ::: "memory");
        else             asm volatile("cp.async.wait_group 0;" ::: "memory");
        __syncthreads();
        if (tid < NCH_S0 * 40) {
            #pragma unroll
            for (int r4 = 0; r4 < 3; r4++) {           // 12 rows = 3 x 4
                __half2 a01 = __float2half2_rn(0.f), a23 = __float2half2_rn(0.f);
                #pragma unroll
                for (int kk = 0; kk < 4; kk++) {
                    const int row = g * 96 + chS * 12 + r4 * 4 + kk;
                    uint2 v = *(const uint2*)(xhb + row * ROWB + q * 8);
                    a01 = __hadd2(a01, *(__half2*)&v.x);
                    a23 = __hadd2(a23, *(__half2*)&v.y);
                }
                float2 f01 = __half22float2(a01), f23 = __half22float2(a23);
                fa.x += f01.x; fa.y += f01.y; fa.z += f23.x; fa.w += f23.y;
            }
        }
    }
    if (tid < NCH_S0 * 40)
        *(float4*)&pacc[chS * OD + q * 4] = fa;
    __syncthreads();

    // ---- exchange 0 (buf0): s0; squash pairs -> t2 regs + th2 ----
    {
        float* slot = (float*)(sm + SLOT0_OFF);
        if (tid < OD) {
            float pv = 0.f;
            #pragma unroll
            for (int c2 = 0; c2 < NCH_S0; c2++) pv += pacc[c2 * OD + tid];
            slot[rank * OD + tid] = pv;
            unsigned int sa = smem_u32(&slot[rank * OD + tid]);
            #pragma unroll
            for (int r = 1; r < CLS; r++) st_remote_f32(sa, rank ^ r, pv);
        }
        cluster_sync_();
        if (tid < 80) {
            float sa = (slot[0 * OD + 2 * tid] + slot[1 * OD + 2 * tid] +
                        slot[2 * OD + 2 * tid] + slot[3 * OD + 2 * tid]) * 0.1f;
            float sb = (slot[0 * OD + 2 * tid + 1] + slot[1 * OD + 2 * tid + 1] +
                        slot[2 * OD + 2 * tid + 1] + slot[3 * OD + 2 * tid + 1]) * 0.1f;
            float v = sa * sa + sb * sb;
            v += __shfl_xor_sync(sqmask, v, 4);
            v += __shfl_xor_sync(sqmask, v, 2);
            v += __shfl_xor_sync(sqmask, v, 1);
            float sc = (v / (1.0f + v)) / (sqrtf(v) + 1e-8f);
            t2.x = sa * sc; t2.y = sb * sc;
            th2[tid] = __floats2half2_rn(t2.x, t2.y);
        }
    }
    __syncthreads();

    // ---- two routing passes ----
    #pragma unroll 1
    for (int pass = 0; pass < 2; pass++) {
        // ===== phase 1: thread = one i (288 threads); half2 dots + softmax
        if (tid < NIH) {
            const char* row = xhb + tid * ROWB;
            float e[NO];
            #pragma unroll
            for (int o = 0; o < NO; o++) {
                uint4 xa = *(const uint4*)(row + o * 32);
                uint4 xb = *(const uint4*)(row + o * 32 + 16);
                uint4 ta = *(const uint4*)((const char*)th2 + o * 32);
                uint4 tb = *(const uint4*)((const char*)th2 + o * 32 + 16);
                __half2 acc = __hmul2(*(__half2*)&xa.x, *(__half2*)&ta.x);
                acc = __hfma2(*(__half2*)&xa.y, *(__half2*)&ta.y, acc);
                acc = __hfma2(*(__half2*)&xa.z, *(__half2*)&ta.z, acc);
                acc = __hfma2(*(__half2*)&xa.w, *(__half2*)&ta.w, acc);
                acc = __hfma2(*(__half2*)&xb.x, *(__half2*)&tb.x, acc);
                acc = __hfma2(*(__half2*)&xb.y, *(__half2*)&tb.y, acc);
                acc = __hfma2(*(__half2*)&xb.z, *(__half2*)&tb.z, acc);
                acc = __hfma2(*(__half2*)&xb.w, *(__half2*)&tb.w, acc);
                float2 f = __half22float2(acc);
                e[o] = f.x + f.y;
            }
            float m = e[0];
            #pragma unroll
            for (int o = 1; o < NO; o++) m = fmaxf(m, e[o]);
            float sum = 0.f;
            #pragma unroll
            for (int o = 0; o < NO; o++) { e[o] = __expf(e[o] - m); sum += e[o]; }
            const float inv = 1.0f / sum;
            __half2* cp = (__half2*)(cbuf + tid * NO);
            #pragma unroll
            for (int p = 0; p < 5; p++)
                cp[p] = __floats2half2_rn(e[2 * p] * inv, e[2 * p + 1] * inv);
        }
        __syncthreads();

        // ===== phase 2: thread = (ch, quad); half2 acc of c*xh, flush/4
        if (tid < NCH_P2 * 40) {
            const int ch = tid / 40;
            float4 pa = make_float4(0.f, 0.f, 0.f, 0.f);
            #pragma unroll
            for (int g4 = 0; g4 < 8; g4++) {
                __half2 a01 = __float2half2_rn(0.f), a23 = __float2half2_rn(0.f);
                #pragma unroll
                for (int kk = 0; kk < 4; kk++) {
                    const int row = ch * 32 + g4 * 4 + kk;
                    uint2 v = *(const uint2*)(xhb + row * ROWB + q * 8);
                    __half2 c2 = __half2half2(cbuf[row * NO + o_q]);
                    a01 = __hfma2(*(__half2*)&v.x, c2, a01);
                    a23 = __hfma2(*(__half2*)&v.y, c2, a23);
                }
                float2 f01 = __half22float2(a01), f23 = __half22float2(a23);
                pa.x += f01.x; pa.y += f01.y; pa.z += f23.x; pa.w += f23.y;
            }
            *(float4*)&pacc[ch * OD + q * 4] = pa;
        }
        __syncthreads();

        // ===== exchange (alternating buffer) + squash pairs
        {
            float* slot = (float*)(sm + ((pass == 0) ? SLOT1_OFF : SLOT0_OFF));
            if (tid < OD) {
                float pv = 0.f;
                #pragma unroll
                for (int c2 = 0; c2 < NCH_P2; c2++) pv += pacc[c2 * OD + tid];
                slot[rank * OD + tid] = pv;
                unsigned int sa = smem_u32(&slot[rank * OD + tid]);
                #pragma unroll
                for (int r = 1; r < CLS; r++) st_remote_f32(sa, rank ^ r, pv);
            }
            cluster_sync_();
            if (tid < 80) {
                float sa = slot[0 * OD + 2 * tid] + slot[1 * OD + 2 * tid] +
                           slot[2 * OD + 2 * tid] + slot[3 * OD + 2 * tid];
                float sb = slot[0 * OD + 2 * tid + 1] + slot[1 * OD + 2 * tid + 1] +
                           slot[2 * OD + 2 * tid + 1] + slot[3 * OD + 2 * tid + 1];
                float v = sa * sa + sb * sb;
                v += __shfl_xor_sync(sqmask, v, 4);
                v += __shfl_xor_sync(sqmask, v, 2);
                v += __shfl_xor_sync(sqmask, v, 1);
                float sc = (v / (1.0f + v)) / (sqrtf(v) + 1e-8f);
                if (pass == 0) {
                    t2.x += sa * sc; t2.y += sb * sc;        // t = out0 + out1
                    th2[tid] = __floats2half2_rn(t2.x, t2.y);
                } else if (rank == 0) {
                    *(float2*)&dout[b * OD + 2 * tid] = make_float2(sa * sc, sb * sc);
                }
            }
        }
        __syncthreads();
    }
}

// =====================================================================
extern "C" void kernel_launch(void* const* d_in, const int* in_sizes, int n_in,
                              void* d_out, int out_size)
{
    const float* x = (const float*)d_in[0];   // [256,1152,8]
    const float* w = (const float*)d_in[1];   // [10,1152,16,8]
    float* out = (float*)d_out;               // [256,10,16]

    cudaFuncSetAttribute(k2_route, cudaFuncAttributeMaxDynamicSharedMemorySize, K2_SMEM);

    k1_xhat<<<dim3(NI / K1_IT, BATCH / K1_BT), 320>>>(x, w);
    k2_route<<<CLS * BATCH, K2_THREADS, K2_SMEM>>>(out);
}